// round 15
// baseline (speedup 1.0000x reference)
#include <cuda_runtime.h>
#include <cuda_fp16.h>
#include <cstdint>

#define NB   8
#define CIN  256
#define HW   4096
#define CATT 128
#define COUT 256

// Scratch (device globals; no allocation allowed)
__device__ __half g_feat_h[(size_t)NB * COUT * HW];  // [n][c][pos] fp16
__device__ __half g_attT_h[(size_t)NB * HW * CATT];  // [n][pos][c] fp16
__device__ float  g_energy[(size_t)NB * HW * HW];    // [n][i][j] f32
__device__ __half g_prob [(size_t)NB * HW * HW];     // softmax(E) fp16
__device__ __half g_xT_h [(size_t)NB * HW * CIN];    // x^T fp16 [n][p][c]
__device__ __half g_w_h  [(size_t)(COUT + CATT) * CIN]; // [feat W ; att W] fp16

// ===========================================================================
// Helpers — family-neutral PTX (sm_80+)
// ===========================================================================
__device__ __forceinline__ uint32_t smem_u32(const void* p) {
    uint32_t a;
    asm("{ .reg .u64 t; cvta.to.shared.u64 t, %1; cvt.u32.u64 %0, t; }" : "=r"(a) : "l"(p));
    return a;
}
__device__ __forceinline__ void mma_f16(float c[4],
        uint32_t a0, uint32_t a1, uint32_t a2, uint32_t a3,
        uint32_t b0, uint32_t b1) {
    asm volatile("mma.sync.aligned.m16n8k16.row.col.f32.f16.f16.f32 "
                 "{%0,%1,%2,%3}, {%4,%5,%6,%7}, {%8,%9}, {%0,%1,%2,%3};"
                 : "+f"(c[0]), "+f"(c[1]), "+f"(c[2]), "+f"(c[3])
                 : "r"(a0), "r"(a1), "r"(a2), "r"(a3), "r"(b0), "r"(b1));
}
#define CP16(dst, src) asm volatile("cp.async.ca.shared.global [%0], [%1], 16;" :: "r"(dst), "l"(src))
#define CP_COMMIT()    asm volatile("cp.async.commit_group;" ::: "memory")
#define CP_WAIT1()     asm volatile("cp.async.wait_group 1;" ::: "memory")
#define CP_WAIT0()     asm volatile("cp.async.wait_group 0;" ::: "memory")

// ===========================================================================
// Kernel 0a: prep X — transpose + fp16: g_xT_h[n][p][c] = rn(x[n][c][p]).
// 64x64 tiles through smem.  grid (HW/64, CIN/64, NB), 256 thr.
// ===========================================================================
__global__ __launch_bounds__(256)
void prep_x_kernel(const float* __restrict__ x) {
    __shared__ float T[64][65];
    const int n = blockIdx.z, c0 = blockIdx.y * 64, p0 = blockIdx.x * 64;
    const int tid = threadIdx.x;
    const float* X = x + ((size_t)n * CIN + c0) * HW + p0;

    #pragma unroll
    for (int idx = tid; idx < 4096; idx += 256) {
        int cc = idx >> 6, pp = idx & 63;
        T[pp][cc] = X[(size_t)cc * HW + pp];
    }
    __syncthreads();
    __half* D = g_xT_h + ((size_t)n * HW + p0) * CIN + c0;
    #pragma unroll
    for (int idx = tid; idx < 2048; idx += 256) {
        int pp = idx >> 5, c2 = idx & 31;
        __half2 h = __floats2half2_rn(T[pp][c2 * 2], T[pp][c2 * 2 + 1]);
        *(__half2*)&D[(size_t)pp * CIN + c2 * 2] = h;
    }
}

// ===========================================================================
// Kernel 0b: prep W — fp16 convert, [feat 256 rows ; att 128 rows] x 256.
// ===========================================================================
__global__ __launch_bounds__(256)
void prep_w_kernel(const float* __restrict__ reduc_w,
                   const float* __restrict__ att_w) {
    int idx = blockIdx.x * 256 + threadIdx.x;   // grid 384 -> 98304
    float v = (idx < COUT * CIN) ? reduc_w[idx] : att_w[idx - COUT * CIN];
    g_w_h[idx] = __float2half_rn(v);
}

// ===========================================================================
// Kernel 1: conv+BN+ReLU via fp16 MMA (clone of out-kernel structure).
// Y[o,p] = sum_c W[o,c]*X^T[p,c].  CTA: M=128(o) x N=256(p), K=256,
// Kt=64 halves, 4 iters, 3-stage cp.async.  grid.y: 0,1 feat; 2 att.
// ===========================================================================
#define V_LD 72
#define V_ABYTES (128 * V_LD * 2)             // 18432
#define V_STAGE  (V_ABYTES + 256 * V_LD * 2)  // 55296
#define V_SMEM   (3 * V_STAGE)                // 165888

__global__ __launch_bounds__(256, 1)
void conv_mma_kernel(const float* __restrict__ reduc_gamma,
                     const float* __restrict__ reduc_beta,
                     const float* __restrict__ reduc_mean,
                     const float* __restrict__ reduc_var,
                     const float* __restrict__ att_gamma,
                     const float* __restrict__ att_beta,
                     const float* __restrict__ att_mean,
                     const float* __restrict__ att_var) {
    extern __shared__ char smc[];
    __shared__ float invS[128], biasS[128];
    const uint32_t sb = smem_u32(smc);
    const int tid = threadIdx.x;
    const int wid = tid >> 5, lane = tid & 31;
    const int n  = blockIdx.z;
    const int p0 = blockIdx.x * 256;
    const int br = blockIdx.y;
    const bool isAtt = (br == 2);
    const __half* W  = g_w_h + (isAtt ? (size_t)COUT * CIN : (size_t)br * 128 * CIN);
    const __half* XT = g_xT_h + (size_t)n * HW * CIN;

    if (tid < 128) {
        int og = isAtt ? tid : br * 128 + tid;
        float g = isAtt ? att_gamma[og] : reduc_gamma[og];
        float v = isAtt ? att_var[og]   : reduc_var[og];
        float b = isAtt ? att_beta[og]  : reduc_beta[og];
        float m = isAtt ? att_mean[og]  : reduc_mean[og];
        float inv = g * rsqrtf(v + 1e-5f);
        invS[tid]  = inv;
        biasS[tid] = b - m * inv;
    }

    auto load_stage = [&](int s, int kt) {
        uint32_t base = sb + (uint32_t)s * V_STAGE;
        #pragma unroll
        for (int idx = tid; idx < 3072; idx += 256) {
            if (idx < 1024) {                  // A: 128 o-rows x 64 c-halves
                int row = idx >> 3, ch = idx & 7;
                CP16(base + row * 144 + ch * 16,
                     W + (size_t)row * CIN + kt + ch * 8);
            } else {                           // B: 256 p-rows x 64 c-halves
                int q = idx - 1024;
                int row = q >> 3, ch = q & 7;
                CP16(base + V_ABYTES + row * 144 + ch * 16,
                     XT + (size_t)(p0 + row) * CIN + kt + ch * 8);
            }
        }
        CP_COMMIT();
    };

    load_stage(0, 0);
    load_stage(1, 64);

    const int wm = wid & 1, wn = wid >> 1;
    const int r = lane >> 2, kq = lane & 3;
    float cc[4][8][4] = {};

    for (int it = 0; it < 4; ++it) {            // K=256 / 64
        CP_WAIT1();
        __syncthreads();
        const __half* As = (const __half*)(smc + (it % 3) * V_STAGE);
        const __half* Bs = (const __half*)(smc + (it % 3) * V_STAGE + V_ABYTES);
        #pragma unroll
        for (int ks = 0; ks < 4; ks++) {
            const int k0 = ks * 16;
            uint32_t af[4][4];
            #pragma unroll
            for (int mt = 0; mt < 4; mt++) {
                int mb = wm * 64 + mt * 16;
                af[mt][0] = *(const uint32_t*)&As[(mb + r) * V_LD + k0 + 2 * kq];
                af[mt][1] = *(const uint32_t*)&As[(mb + r + 8) * V_LD + k0 + 2 * kq];
                af[mt][2] = *(const uint32_t*)&As[(mb + r) * V_LD + k0 + 2 * kq + 8];
                af[mt][3] = *(const uint32_t*)&As[(mb + r + 8) * V_LD + k0 + 2 * kq + 8];
            }
            #pragma unroll
            for (int nt = 0; nt < 8; nt++) {
                int nb = wn * 64 + nt * 8;
                uint32_t b0 = *(const uint32_t*)&Bs[(nb + r) * V_LD + k0 + 2 * kq];
                uint32_t b1 = *(const uint32_t*)&Bs[(nb + r) * V_LD + k0 + 2 * kq + 8];
                #pragma unroll
                for (int mt = 0; mt < 4; mt++)
                    mma_f16(cc[mt][nt], af[mt][0], af[mt][1], af[mt][2], af[mt][3], b0, b1);
            }
        }
        __syncthreads();
        if (it + 2 < 4) load_stage((it + 2) % 3, (it + 2) * 64);
        else CP_COMMIT();
    }
    CP_WAIT0();
    __syncthreads();

    // BN + ReLU in registers
    #pragma unroll
    for (int mt = 0; mt < 4; mt++) {
        int ob = wm * 64 + mt * 16 + r;
        float i0 = invS[ob],     b0 = biasS[ob];
        float i1 = invS[ob + 8], b1 = biasS[ob + 8];
        #pragma unroll
        for (int nt = 0; nt < 8; nt++) {
            cc[mt][nt][0] = fmaxf(fmaf(cc[mt][nt][0], i0, b0), 0.0f);
            cc[mt][nt][1] = fmaxf(fmaf(cc[mt][nt][1], i0, b0), 0.0f);
            cc[mt][nt][2] = fmaxf(fmaf(cc[mt][nt][2], i1, b1), 0.0f);
            cc[mt][nt][3] = fmaxf(fmaf(cc[mt][nt][3], i1, b1), 0.0f);
        }
    }

    float* S = (float*)smc;
    if (!isAtt) {
        // Stage S[o][p] (pad 260); fp16 store over p.
        #pragma unroll
        for (int mt = 0; mt < 4; mt++) {
            int ob = wm * 64 + mt * 16 + r;
            #pragma unroll
            for (int nt = 0; nt < 8; nt++) {
                int pb = wn * 64 + nt * 8 + kq * 2;
                S[ob * 260 + pb]           = cc[mt][nt][0];
                S[ob * 260 + pb + 1]       = cc[mt][nt][1];
                S[(ob + 8) * 260 + pb]     = cc[mt][nt][2];
                S[(ob + 8) * 260 + pb + 1] = cc[mt][nt][3];
            }
        }
        __syncthreads();
        #pragma unroll 4
        for (int idx = tid; idx < 8192; idx += 256) {
            int row = idx >> 6, ch = idx & 63;
            float4 v = *(const float4*)&S[row * 260 + ch * 4];
            __half2 h0 = __floats2half2_rn(v.x, v.y);
            __half2 h1 = __floats2half2_rn(v.z, v.w);
            *(uint2*)&g_feat_h[((size_t)n * COUT + br * 128 + row) * HW + p0 + ch * 4]
                = make_uint2(*(uint32_t*)&h0, *(uint32_t*)&h1);
        }
    } else {
        // Stage transposed S[p][o] (pad 132); fp16 store over c.
        #pragma unroll
        for (int mt = 0; mt < 4; mt++) {
            int ob = wm * 64 + mt * 16 + r;
            #pragma unroll
            for (int nt = 0; nt < 8; nt++) {
                int pb = wn * 64 + nt * 8 + kq * 2;
                S[pb * 132 + ob]           = cc[mt][nt][0];
                S[(pb + 1) * 132 + ob]     = cc[mt][nt][1];
                S[pb * 132 + ob + 8]       = cc[mt][nt][2];
                S[(pb + 1) * 132 + ob + 8] = cc[mt][nt][3];
            }
        }
        __syncthreads();
        #pragma unroll 4
        for (int idx = tid; idx < 8192; idx += 256) {
            int row = idx >> 5, ch = idx & 31;     // 256 p-rows x 128 c
            float4 v = *(const float4*)&S[row * 132 + ch * 4];
            __half2 h0 = __floats2half2_rn(v.x, v.y);
            __half2 h1 = __floats2half2_rn(v.z, v.w);
            *(uint2*)&g_attT_h[((size_t)n * HW + p0 + row) * CATT + ch * 4]
                = make_uint2(*(uint32_t*)&h0, *(uint32_t*)&h1);
        }
    }
}

// ===========================================================================
// Kernel 2: energy via fp16 mma, SYMMETRIC — only upper-triangular tiles.
// Tile (ti: 128 i-rows, tJ: 256 j-cols), launched iff tJ >= ti/2.
// Each CTA writes its tile directly AND the transposed mirror tile.
// Overlap cells are written with bitwise-identical values -> benign.
// ===========================================================================
#define EH_LD 136
#define E_SLD 260
#define E_SMEM 136192
#define E_NCTA 272   // sum over ti of (16 - ti/2)

__global__ __launch_bounds__(256, 1)
void energy_mma_kernel(const float* __restrict__ mask) {
    extern __shared__ char sme[];
    __half* As = (__half*)sme;                  // 128 x EH_LD
    __half* Bs = (__half*)sme + 128 * EH_LD;    // 256 x EH_LD

    const int tid  = threadIdx.x;
    const int wid  = tid >> 5, lane = tid & 31;
    const int n  = blockIdx.y;

    // Decode upper-triangular tile index
    int lin = blockIdx.x, ti = 0;
    #pragma unroll 1
    for (ti = 0; ti < 32; ti++) {
        int c = 16 - (ti >> 1);
        if (lin < c) break;
        lin -= c;
    }
    const int tJ = (ti >> 1) + lin;
    const int i0 = ti * 128, j0 = tJ * 256;
    const __half* attn = g_attT_h + (size_t)n * HW * CATT;

    #pragma unroll 4
    for (int idx = tid; idx < 2048; idx += 256) {   // A: 128 rows x 16 uint4
        int row = idx >> 4, ch = idx & 15;
        *(uint4*)&As[row * EH_LD + ch * 8] =
            *(const uint4*)(attn + (size_t)(i0 + row) * CATT + ch * 8);
    }
    #pragma unroll 4
    for (int idx = tid; idx < 4096; idx += 256) {   // B: 256 rows x 16 uint4
        int row = idx >> 4, ch = idx & 15;
        *(uint4*)&Bs[row * EH_LD + ch * 8] =
            *(const uint4*)(attn + (size_t)(j0 + row) * CATT + ch * 8);
    }
    __syncthreads();

    const int wm = wid & 1, wn = wid >> 1;
    const int r = lane >> 2, kq = lane & 3;
    float cc[4][8][4] = {};

    #pragma unroll
    for (int ks = 0; ks < 8; ks++) {
        const int k0 = ks * 16;
        uint32_t af[4][4];
        #pragma unroll
        for (int mt = 0; mt < 4; mt++) {
            int mb = wm * 64 + mt * 16;
            af[mt][0] = *(const uint32_t*)&As[(mb + r) * EH_LD + k0 + 2 * kq];
            af[mt][1] = *(const uint32_t*)&As[(mb + r + 8) * EH_LD + k0 + 2 * kq];
            af[mt][2] = *(const uint32_t*)&As[(mb + r) * EH_LD + k0 + 2 * kq + 8];
            af[mt][3] = *(const uint32_t*)&As[(mb + r + 8) * EH_LD + k0 + 2 * kq + 8];
        }
        #pragma unroll
        for (int nt = 0; nt < 8; nt++) {
            int nb = wn * 64 + nt * 8;
            uint32_t b0 = *(const uint32_t*)&Bs[(nb + r) * EH_LD + k0 + 2 * kq];
            uint32_t b1 = *(const uint32_t*)&Bs[(nb + r) * EH_LD + k0 + 2 * kq + 8];
            #pragma unroll
            for (int mt = 0; mt < 4; mt++)
                mma_f16(cc[mt][nt], af[mt][0], af[mt][1], af[mt][2], af[mt][3], b0, b1);
        }
    }
    __syncthreads();

    // Stage RAW C: S[i_local][j_local], stride E_SLD.
    float* S = (float*)sme;
    #pragma unroll
    for (int mt = 0; mt < 4; mt++) {
        int ib = wm * 64 + mt * 16 + r;
        #pragma unroll
        for (int nt = 0; nt < 8; nt++) {
            int jb = wn * 64 + nt * 8 + kq * 2;
            S[ib * E_SLD + jb]           = cc[mt][nt][0];
            S[ib * E_SLD + jb + 1]       = cc[mt][nt][1];
            S[(ib + 8) * E_SLD + jb]     = cc[mt][nt][2];
            S[(ib + 8) * E_SLD + jb + 1] = cc[mt][nt][3];
        }
    }
    __syncthreads();

    const float inv_s = 0.08838834764831845f;   // 1/(1e-8+sqrt(128))

    // Direct tile: E[i0+row][j0+...] with column mask term over j.
    #pragma unroll 4
    for (int idx = tid; idx < 8192; idx += 256) {
        int row = idx >> 6, ch = idx & 63;
        int j = j0 + ch * 4;
        float4 v = *(const float4*)&S[row * E_SLD + ch * 4];
        float4 mm = *(const float4*)&mask[(size_t)n * HW + j];
        v.x = v.x * inv_s + (mm.x - 1.0f) * 1e8f;
        v.y = v.y * inv_s + (mm.y - 1.0f) * 1e8f;
        v.z = v.z * inv_s + (mm.z - 1.0f) * 1e8f;
        v.w = v.w * inv_s + (mm.w - 1.0f) * 1e8f;
        *(float4*)&g_energy[((size_t)n * HW + i0 + row) * HW + j] = v;
    }

    // Mirror tile: E[j0+jj][i0+ii] with column mask term over i.
    #pragma unroll 4
    for (int idx = tid; idx < 8192; idx += 256) {
        int jj = idx >> 5, ii = (idx & 31) * 4;
        float4 mm = *(const float4*)&mask[(size_t)n * HW + i0 + ii];
        float4 v;
        v.x = S[(ii + 0) * E_SLD + jj] * inv_s + (mm.x - 1.0f) * 1e8f;
        v.y = S[(ii + 1) * E_SLD + jj] * inv_s + (mm.y - 1.0f) * 1e8f;
        v.z = S[(ii + 2) * E_SLD + jj] * inv_s + (mm.z - 1.0f) * 1e8f;
        v.w = S[(ii + 3) * E_SLD + jj] * inv_s + (mm.w - 1.0f) * 1e8f;
        *(float4*)&g_energy[((size_t)n * HW + j0 + jj) * HW + i0 + ii] = v;
    }
}

// ===========================================================================
// Kernel 3: row softmax — f32 in, fp16 probs out (unchanged).
// ===========================================================================
__global__ void softmax_kernel() {
    const size_t row = blockIdx.x;
    const float* E = g_energy + row * HW;
    __half* P = g_prob + row * HW;
    const int tid = threadIdx.x;

    float2 v[8];
    float m = -1e30f;
    #pragma unroll
    for (int t = 0; t < 8; t++) {
        v[t] = *(const float2*)&E[t * 512 + tid * 2];
        m = fmaxf(m, fmaxf(v[t].x, v[t].y));
    }
    __shared__ float sred[8];
    #pragma unroll
    for (int o = 16; o > 0; o >>= 1)
        m = fmaxf(m, __shfl_xor_sync(0xffffffffu, m, o));
    if ((tid & 31) == 0) sred[tid >> 5] = m;
    __syncthreads();
    float mAll = sred[0];
    #pragma unroll
    for (int w = 1; w < 8; w++) mAll = fmaxf(mAll, sred[w]);

    float s = 0.0f;
    #pragma unroll
    for (int t = 0; t < 8; t++) {
        v[t].x = __expf(v[t].x - mAll);
        v[t].y = __expf(v[t].y - mAll);
        s += v[t].x + v[t].y;
    }
    #pragma unroll
    for (int o = 16; o > 0; o >>= 1)
        s += __shfl_xor_sync(0xffffffffu, s, o);
    __syncthreads();
    if ((tid & 31) == 0) sred[tid >> 5] = s;
    __syncthreads();
    float sAll = 0.0f;
    #pragma unroll
    for (int w = 0; w < 8; w++) sAll += sred[w];

    const float rr = 1.0f / sAll;
    #pragma unroll
    for (int t = 0; t < 8; t++) {
        __half2 h = __floats2half2_rn(v[t].x * rr, v[t].y * rr);
        *(__half2*)&P[t * 512 + tid * 2] = h;
    }
}

// ===========================================================================
// Kernel 4: out = prob @ feat^T via fp16 mma + cp.async 3-stage (unchanged).
// CTA: M=128(i) x N=256(c), K=4096 (Kt=64 halves, 64 iters).
// ===========================================================================
#define OH_LD 72
#define O_ABYTES (128 * OH_LD * 2)
#define O_STAGE  (O_ABYTES + 256 * OH_LD * 2)  // 55296
#define O_SMEM   (3 * O_STAGE)                 // 165888
#define O_NIT    64

__global__ __launch_bounds__(256, 1)
void out_mma_kernel(const float* __restrict__ mask, float* __restrict__ out) {
    extern __shared__ char smc[];
    const uint32_t sb = smem_u32(smc);
    const int tid  = threadIdx.x;
    const int wid  = tid >> 5, lane = tid & 31;
    const int n  = blockIdx.y;
    const int i0 = blockIdx.x * 128;
    const __half* Pg = g_prob   + (size_t)n * HW * HW;   // [i][j]
    const __half* F  = g_feat_h + (size_t)n * COUT * HW; // [c][j]

    auto load_stage = [&](int s, int kt) {
        uint32_t base = sb + (uint32_t)s * O_STAGE;
        #pragma unroll
        for (int idx = tid; idx < 3072; idx += 256) {
            if (idx < 1024) {
                int row = idx >> 3, ch = idx & 7;
                CP16(base + row * 144 + ch * 16,
                     Pg + (size_t)(i0 + row) * HW + kt + ch * 8);
            } else {
                int q = idx - 1024;
                int row = q >> 3, ch = q & 7;
                CP16(base + O_ABYTES + row * 144 + ch * 16,
                     F + (size_t)row * HW + kt + ch * 8);
            }
        }
        CP_COMMIT();
    };

    load_stage(0, 0);
    load_stage(1, 64);

    const int wm = wid & 1, wn = wid >> 1;
    const int r = lane >> 2, kq = lane & 3;
    float cc[4][8][4] = {};

    for (int it = 0; it < O_NIT; ++it) {
        CP_WAIT1();
        __syncthreads();
        const __half* As = (const __half*)(smc + (it % 3) * O_STAGE);
        const __half* Bs = (const __half*)(smc + (it % 3) * O_STAGE + O_ABYTES);
        #pragma unroll
        for (int ks = 0; ks < 4; ks++) {
            const int k0 = ks * 16;
            uint32_t af[4][4];
            #pragma unroll
            for (int mt = 0; mt < 4; mt++) {
                int mb = wm * 64 + mt * 16;
                af[mt][0] = *(const uint32_t*)&As[(mb + r) * OH_LD + k0 + 2 * kq];
                af[mt][1] = *(const uint32_t*)&As[(mb + r + 8) * OH_LD + k0 + 2 * kq];
                af[mt][2] = *(const uint32_t*)&As[(mb + r) * OH_LD + k0 + 2 * kq + 8];
                af[mt][3] = *(const uint32_t*)&As[(mb + r + 8) * OH_LD + k0 + 2 * kq + 8];
            }
            #pragma unroll
            for (int nt = 0; nt < 8; nt++) {
                int nb = wn * 64 + nt * 8;
                uint32_t b0 = *(const uint32_t*)&Bs[(nb + r) * OH_LD + k0 + 2 * kq];
                uint32_t b1 = *(const uint32_t*)&Bs[(nb + r) * OH_LD + k0 + 2 * kq + 8];
                #pragma unroll
                for (int mt = 0; mt < 4; mt++)
                    mma_f16(cc[mt][nt], af[mt][0], af[mt][1], af[mt][2], af[mt][3], b0, b1);
            }
        }
        __syncthreads();
        if (it + 2 < O_NIT) load_stage((it + 2) % 3, (it + 2) * 64);
        else CP_COMMIT();
    }
    CP_WAIT0();
    __syncthreads();

    // Stage C: S[c_local][i_local], stride 132; masked f32 store.
    float* S = (float*)smc;
    #pragma unroll
    for (int mt = 0; mt < 4; mt++) {
        int ib = wm * 64 + mt * 16 + r;
        #pragma unroll
        for (int nt = 0; nt < 8; nt++) {
            int cb = wn * 64 + nt * 8 + kq * 2;
            S[cb * 132 + ib]           = cc[mt][nt][0];
            S[(cb + 1) * 132 + ib]     = cc[mt][nt][1];
            S[cb * 132 + ib + 8]       = cc[mt][nt][2];
            S[(cb + 1) * 132 + ib + 8] = cc[mt][nt][3];
        }
    }
    __syncthreads();

    #pragma unroll 4
    for (int idx = tid; idx < 8192; idx += 256) {
        int row = idx >> 5, ch = idx & 31;
        int ii = i0 + ch * 4;
        float4 v = *(const float4*)&S[row * 132 + ch * 4];
        float4 mm = *(const float4*)&mask[(size_t)n * HW + ii];
        v.x *= mm.x; v.y *= mm.y; v.z *= mm.z; v.w *= mm.w;
        *(float4*)&out[((size_t)n * COUT + row) * HW + ii] = v;
    }
}

// ===========================================================================
extern "C" void kernel_launch(void* const* d_in, const int* in_sizes, int n_in,
                              void* d_out, int out_size) {
    const float* x           = (const float*)d_in[0];
    const float* mask        = (const float*)d_in[1];
    const float* reduc_w     = (const float*)d_in[2];
    const float* reduc_gamma = (const float*)d_in[3];
    const float* reduc_beta  = (const float*)d_in[4];
    const float* reduc_mean  = (const float*)d_in[5];
    const float* reduc_var   = (const float*)d_in[6];
    const float* att_w       = (const float*)d_in[7];
    const float* att_gamma   = (const float*)d_in[8];
    const float* att_beta    = (const float*)d_in[9];
    const float* att_mean    = (const float*)d_in[10];
    const float* att_var     = (const float*)d_in[11];
    float* out = (float*)d_out;

    cudaFuncSetAttribute(conv_mma_kernel,   cudaFuncAttributeMaxDynamicSharedMemorySize, V_SMEM);
    cudaFuncSetAttribute(energy_mma_kernel, cudaFuncAttributeMaxDynamicSharedMemorySize, E_SMEM);
    cudaFuncSetAttribute(out_mma_kernel,    cudaFuncAttributeMaxDynamicSharedMemorySize, O_SMEM);

    prep_x_kernel<<<dim3(HW / 64, CIN / 64, NB), 256>>>(x);
    prep_w_kernel<<<384, 256>>>(reduc_w, att_w);

    conv_mma_kernel<<<dim3(HW / 256, 3, NB), 256, V_SMEM>>>(
        reduc_gamma, reduc_beta, reduc_mean, reduc_var,
        att_gamma, att_beta, att_mean, att_var);

    energy_mma_kernel<<<dim3(E_NCTA, NB), 256, E_SMEM>>>(mask);

    softmax_kernel<<<NB * HW, 256>>>();

    out_mma_kernel<<<dim3(HW / 128, NB), 256, O_SMEM>>>(mask, out);
}

// round 16
// speedup vs baseline: 1.0796x; 1.0796x over previous
#include <cuda_runtime.h>
#include <cuda_fp16.h>
#include <cstdint>

#define NB   8
#define CIN  256
#define HW   4096
#define CATT 128
#define COUT 256

// Scratch (device globals; no allocation allowed)
__device__ __half g_feat_h[(size_t)NB * COUT * HW];  // [n][c][pos] fp16
__device__ __half g_attT_h[(size_t)NB * HW * CATT];  // [n][pos][c] fp16
__device__ float  g_energy[(size_t)NB * HW * HW];    // [n][i][j] f32
__device__ __half g_prob [(size_t)NB * HW * HW];     // softmax(E) fp16
__device__ __half g_xT_h [(size_t)NB * HW * CIN];    // x^T fp16 [n][p][c]
__device__ __half g_w_h  [(size_t)(COUT + CATT) * CIN]; // [feat W ; att W] fp16

// ===========================================================================
// Helpers — family-neutral PTX (sm_80+)
// ===========================================================================
__device__ __forceinline__ uint32_t smem_u32(const void* p) {
    uint32_t a;
    asm("{ .reg .u64 t; cvta.to.shared.u64 t, %1; cvt.u32.u64 %0, t; }" : "=r"(a) : "l"(p));
    return a;
}
__device__ __forceinline__ void mma_f16(float c[4],
        uint32_t a0, uint32_t a1, uint32_t a2, uint32_t a3,
        uint32_t b0, uint32_t b1) {
    asm volatile("mma.sync.aligned.m16n8k16.row.col.f32.f16.f16.f32 "
                 "{%0,%1,%2,%3}, {%4,%5,%6,%7}, {%8,%9}, {%0,%1,%2,%3};"
                 : "+f"(c[0]), "+f"(c[1]), "+f"(c[2]), "+f"(c[3])
                 : "r"(a0), "r"(a1), "r"(a2), "r"(a3), "r"(b0), "r"(b1));
}
#define CP16(dst, src) asm volatile("cp.async.ca.shared.global [%0], [%1], 16;" :: "r"(dst), "l"(src))
#define CP_COMMIT()    asm volatile("cp.async.commit_group;" ::: "memory")
#define CP_WAIT1()     asm volatile("cp.async.wait_group 1;" ::: "memory")
#define CP_WAIT0()     asm volatile("cp.async.wait_group 0;" ::: "memory")

// ===========================================================================
// Kernel 0a: prep X — transpose + fp16: g_xT_h[n][p][c] = rn(x[n][c][p]).
// ===========================================================================
__global__ __launch_bounds__(256)
void prep_x_kernel(const float* __restrict__ x) {
    __shared__ float T[64][65];
    const int n = blockIdx.z, c0 = blockIdx.y * 64, p0 = blockIdx.x * 64;
    const int tid = threadIdx.x;
    const float* X = x + ((size_t)n * CIN + c0) * HW + p0;

    #pragma unroll
    for (int idx = tid; idx < 4096; idx += 256) {
        int cc = idx >> 6, pp = idx & 63;
        T[pp][cc] = X[(size_t)cc * HW + pp];
    }
    __syncthreads();
    __half* D = g_xT_h + ((size_t)n * HW + p0) * CIN + c0;
    #pragma unroll
    for (int idx = tid; idx < 2048; idx += 256) {
        int pp = idx >> 5, c2 = idx & 31;
        __half2 h = __floats2half2_rn(T[pp][c2 * 2], T[pp][c2 * 2 + 1]);
        *(__half2*)&D[(size_t)pp * CIN + c2 * 2] = h;
    }
}

// ===========================================================================
// Kernel 0b: prep W — fp16 convert.
// ===========================================================================
__global__ __launch_bounds__(256)
void prep_w_kernel(const float* __restrict__ reduc_w,
                   const float* __restrict__ att_w) {
    int idx = blockIdx.x * 256 + threadIdx.x;   // grid 384 -> 98304
    float v = (idx < COUT * CIN) ? reduc_w[idx] : att_w[idx - COUT * CIN];
    g_w_h[idx] = __float2half_rn(v);
}

// ===========================================================================
// Kernel 1: conv+BN+ReLU via fp16 MMA (R15, kept).
// CTA: M=128(o) x N=256(p), K=256, Kt=64 halves, 3-stage cp.async.
// grid.y: 0,1 feat; 2 att (transposed out).
// ===========================================================================
#define V_LD 72
#define V_ABYTES (128 * V_LD * 2)             // 18432
#define V_STAGE  (V_ABYTES + 256 * V_LD * 2)  // 55296
#define V_SMEM   (3 * V_STAGE)                // 165888

__global__ __launch_bounds__(256, 1)
void conv_mma_kernel(const float* __restrict__ reduc_gamma,
                     const float* __restrict__ reduc_beta,
                     const float* __restrict__ reduc_mean,
                     const float* __restrict__ reduc_var,
                     const float* __restrict__ att_gamma,
                     const float* __restrict__ att_beta,
                     const float* __restrict__ att_mean,
                     const float* __restrict__ att_var) {
    extern __shared__ char smc[];
    __shared__ float invS[128], biasS[128];
    const uint32_t sb = smem_u32(smc);
    const int tid = threadIdx.x;
    const int wid = tid >> 5, lane = tid & 31;
    const int n  = blockIdx.z;
    const int p0 = blockIdx.x * 256;
    const int br = blockIdx.y;
    const bool isAtt = (br == 2);
    const __half* W  = g_w_h + (isAtt ? (size_t)COUT * CIN : (size_t)br * 128 * CIN);
    const __half* XT = g_xT_h + (size_t)n * HW * CIN;

    if (tid < 128) {
        int og = isAtt ? tid : br * 128 + tid;
        float g = isAtt ? att_gamma[og] : reduc_gamma[og];
        float v = isAtt ? att_var[og]   : reduc_var[og];
        float b = isAtt ? att_beta[og]  : reduc_beta[og];
        float m = isAtt ? att_mean[og]  : reduc_mean[og];
        float inv = g * rsqrtf(v + 1e-5f);
        invS[tid]  = inv;
        biasS[tid] = b - m * inv;
    }

    auto load_stage = [&](int s, int kt) {
        uint32_t base = sb + (uint32_t)s * V_STAGE;
        #pragma unroll
        for (int idx = tid; idx < 3072; idx += 256) {
            if (idx < 1024) {
                int row = idx >> 3, ch = idx & 7;
                CP16(base + row * 144 + ch * 16,
                     W + (size_t)row * CIN + kt + ch * 8);
            } else {
                int q = idx - 1024;
                int row = q >> 3, ch = q & 7;
                CP16(base + V_ABYTES + row * 144 + ch * 16,
                     XT + (size_t)(p0 + row) * CIN + kt + ch * 8);
            }
        }
        CP_COMMIT();
    };

    load_stage(0, 0);
    load_stage(1, 64);

    const int wm = wid & 1, wn = wid >> 1;
    const int r = lane >> 2, kq = lane & 3;
    float cc[4][8][4] = {};

    for (int it = 0; it < 4; ++it) {            // K=256 / 64
        CP_WAIT1();
        __syncthreads();
        const __half* As = (const __half*)(smc + (it % 3) * V_STAGE);
        const __half* Bs = (const __half*)(smc + (it % 3) * V_STAGE + V_ABYTES);
        #pragma unroll
        for (int ks = 0; ks < 4; ks++) {
            const int k0 = ks * 16;
            uint32_t af[4][4];
            #pragma unroll
            for (int mt = 0; mt < 4; mt++) {
                int mb = wm * 64 + mt * 16;
                af[mt][0] = *(const uint32_t*)&As[(mb + r) * V_LD + k0 + 2 * kq];
                af[mt][1] = *(const uint32_t*)&As[(mb + r + 8) * V_LD + k0 + 2 * kq];
                af[mt][2] = *(const uint32_t*)&As[(mb + r) * V_LD + k0 + 2 * kq + 8];
                af[mt][3] = *(const uint32_t*)&As[(mb + r + 8) * V_LD + k0 + 2 * kq + 8];
            }
            #pragma unroll
            for (int nt = 0; nt < 8; nt++) {
                int nb = wn * 64 + nt * 8;
                uint32_t b0 = *(const uint32_t*)&Bs[(nb + r) * V_LD + k0 + 2 * kq];
                uint32_t b1 = *(const uint32_t*)&Bs[(nb + r) * V_LD + k0 + 2 * kq + 8];
                #pragma unroll
                for (int mt = 0; mt < 4; mt++)
                    mma_f16(cc[mt][nt], af[mt][0], af[mt][1], af[mt][2], af[mt][3], b0, b1);
            }
        }
        __syncthreads();
        if (it + 2 < 4) load_stage((it + 2) % 3, (it + 2) * 64);
        else CP_COMMIT();
    }
    CP_WAIT0();
    __syncthreads();

    // BN + ReLU in registers
    #pragma unroll
    for (int mt = 0; mt < 4; mt++) {
        int ob = wm * 64 + mt * 16 + r;
        float i0 = invS[ob],     b0 = biasS[ob];
        float i1 = invS[ob + 8], b1 = biasS[ob + 8];
        #pragma unroll
        for (int nt = 0; nt < 8; nt++) {
            cc[mt][nt][0] = fmaxf(fmaf(cc[mt][nt][0], i0, b0), 0.0f);
            cc[mt][nt][1] = fmaxf(fmaf(cc[mt][nt][1], i0, b0), 0.0f);
            cc[mt][nt][2] = fmaxf(fmaf(cc[mt][nt][2], i1, b1), 0.0f);
            cc[mt][nt][3] = fmaxf(fmaf(cc[mt][nt][3], i1, b1), 0.0f);
        }
    }

    float* S = (float*)smc;
    if (!isAtt) {
        #pragma unroll
        for (int mt = 0; mt < 4; mt++) {
            int ob = wm * 64 + mt * 16 + r;
            #pragma unroll
            for (int nt = 0; nt < 8; nt++) {
                int pb = wn * 64 + nt * 8 + kq * 2;
                S[ob * 260 + pb]           = cc[mt][nt][0];
                S[ob * 260 + pb + 1]       = cc[mt][nt][1];
                S[(ob + 8) * 260 + pb]     = cc[mt][nt][2];
                S[(ob + 8) * 260 + pb + 1] = cc[mt][nt][3];
            }
        }
        __syncthreads();
        #pragma unroll 4
        for (int idx = tid; idx < 8192; idx += 256) {
            int row = idx >> 6, ch = idx & 63;
            float4 v = *(const float4*)&S[row * 260 + ch * 4];
            __half2 h0 = __floats2half2_rn(v.x, v.y);
            __half2 h1 = __floats2half2_rn(v.z, v.w);
            *(uint2*)&g_feat_h[((size_t)n * COUT + br * 128 + row) * HW + p0 + ch * 4]
                = make_uint2(*(uint32_t*)&h0, *(uint32_t*)&h1);
        }
    } else {
        #pragma unroll
        for (int mt = 0; mt < 4; mt++) {
            int ob = wm * 64 + mt * 16 + r;
            #pragma unroll
            for (int nt = 0; nt < 8; nt++) {
                int pb = wn * 64 + nt * 8 + kq * 2;
                S[pb * 132 + ob]           = cc[mt][nt][0];
                S[(pb + 1) * 132 + ob]     = cc[mt][nt][1];
                S[pb * 132 + ob + 8]       = cc[mt][nt][2];
                S[(pb + 1) * 132 + ob + 8] = cc[mt][nt][3];
            }
        }
        __syncthreads();
        #pragma unroll 4
        for (int idx = tid; idx < 8192; idx += 256) {
            int row = idx >> 5, ch = idx & 31;
            float4 v = *(const float4*)&S[row * 132 + ch * 4];
            __half2 h0 = __floats2half2_rn(v.x, v.y);
            __half2 h1 = __floats2half2_rn(v.z, v.w);
            *(uint2*)&g_attT_h[((size_t)n * HW + p0 + row) * CATT + ch * 4]
                = make_uint2(*(uint32_t*)&h0, *(uint32_t*)&h1);
        }
    }
}

// ===========================================================================
// Kernel 2 (R14, verbatim): energy via fp16 mma (m16n8k16).
// CTA: 128(i) x 256(j), K=128 (8 k16-steps). 8 warps 2x4, warp tile 64x64.
// ===========================================================================
#define EH_LD 136
#define E_SLD 260
#define E_SMEM 136192

__global__ __launch_bounds__(256, 1)
void energy_mma_kernel(const float* __restrict__ mask) {
    extern __shared__ char sme[];
    __half* As = (__half*)sme;                  // 128 x EH_LD
    __half* Bs = (__half*)sme + 128 * EH_LD;    // 256 x EH_LD

    const int tid  = threadIdx.x;
    const int wid  = tid >> 5, lane = tid & 31;
    const int n  = blockIdx.z;
    const int i0 = blockIdx.y * 128;
    const int j0 = blockIdx.x * 256;
    const __half* attn = g_attT_h + (size_t)n * HW * CATT;

    #pragma unroll 4
    for (int idx = tid; idx < 2048; idx += 256) {   // A: 128 rows x 16 uint4
        int row = idx >> 4, ch = idx & 15;
        *(uint4*)&As[row * EH_LD + ch * 8] =
            *(const uint4*)(attn + (size_t)(i0 + row) * CATT + ch * 8);
    }
    #pragma unroll 4
    for (int idx = tid; idx < 4096; idx += 256) {   // B: 256 rows x 16 uint4
        int row = idx >> 4, ch = idx & 15;
        *(uint4*)&Bs[row * EH_LD + ch * 8] =
            *(const uint4*)(attn + (size_t)(j0 + row) * CATT + ch * 8);
    }
    __syncthreads();

    const int wm = wid & 1, wn = wid >> 1;
    const int r = lane >> 2, kq = lane & 3;
    float cc[4][8][4] = {};

    #pragma unroll
    for (int ks = 0; ks < 8; ks++) {
        const int k0 = ks * 16;
        uint32_t af[4][4];
        #pragma unroll
        for (int mt = 0; mt < 4; mt++) {
            int mb = wm * 64 + mt * 16;
            af[mt][0] = *(const uint32_t*)&As[(mb + r) * EH_LD + k0 + 2 * kq];
            af[mt][1] = *(const uint32_t*)&As[(mb + r + 8) * EH_LD + k0 + 2 * kq];
            af[mt][2] = *(const uint32_t*)&As[(mb + r) * EH_LD + k0 + 2 * kq + 8];
            af[mt][3] = *(const uint32_t*)&As[(mb + r + 8) * EH_LD + k0 + 2 * kq + 8];
        }
        #pragma unroll
        for (int nt = 0; nt < 8; nt++) {
            int nb = wn * 64 + nt * 8;
            uint32_t b0 = *(const uint32_t*)&Bs[(nb + r) * EH_LD + k0 + 2 * kq];
            uint32_t b1 = *(const uint32_t*)&Bs[(nb + r) * EH_LD + k0 + 2 * kq + 8];
            #pragma unroll
            for (int mt = 0; mt < 4; mt++)
                mma_f16(cc[mt][nt], af[mt][0], af[mt][1], af[mt][2], af[mt][3], b0, b1);
        }
    }
    __syncthreads();

    // Stage C f32: S[i_local][j_local], stride E_SLD; then scale+mask store.
    float* S = (float*)sme;
    #pragma unroll
    for (int mt = 0; mt < 4; mt++) {
        int ib = wm * 64 + mt * 16 + r;
        #pragma unroll
        for (int nt = 0; nt < 8; nt++) {
            int jb = wn * 64 + nt * 8 + kq * 2;
            S[ib * E_SLD + jb]           = cc[mt][nt][0];
            S[ib * E_SLD + jb + 1]       = cc[mt][nt][1];
            S[(ib + 8) * E_SLD + jb]     = cc[mt][nt][2];
            S[(ib + 8) * E_SLD + jb + 1] = cc[mt][nt][3];
        }
    }
    __syncthreads();

    const float inv_s = 0.08838834764831845f;   // 1/(1e-8+sqrt(128))
    #pragma unroll 4
    for (int idx = tid; idx < 8192; idx += 256) {
        int row = idx >> 6, ch = idx & 63;
        int j = j0 + ch * 4;
        float4 v = *(const float4*)&S[row * E_SLD + ch * 4];
        float4 mm = *(const float4*)&mask[(size_t)n * HW + j];
        v.x = v.x * inv_s + (mm.x - 1.0f) * 1e8f;
        v.y = v.y * inv_s + (mm.y - 1.0f) * 1e8f;
        v.z = v.z * inv_s + (mm.z - 1.0f) * 1e8f;
        v.w = v.w * inv_s + (mm.w - 1.0f) * 1e8f;
        *(float4*)&g_energy[((size_t)n * HW + i0 + row) * HW + j] = v;
    }
}

// ===========================================================================
// Kernel 3: row softmax — f32 in, fp16 probs out (unchanged).
// ===========================================================================
__global__ void softmax_kernel() {
    const size_t row = blockIdx.x;
    const float* E = g_energy + row * HW;
    __half* P = g_prob + row * HW;
    const int tid = threadIdx.x;

    float2 v[8];
    float m = -1e30f;
    #pragma unroll
    for (int t = 0; t < 8; t++) {
        v[t] = *(const float2*)&E[t * 512 + tid * 2];
        m = fmaxf(m, fmaxf(v[t].x, v[t].y));
    }
    __shared__ float sred[8];
    #pragma unroll
    for (int o = 16; o > 0; o >>= 1)
        m = fmaxf(m, __shfl_xor_sync(0xffffffffu, m, o));
    if ((tid & 31) == 0) sred[tid >> 5] = m;
    __syncthreads();
    float mAll = sred[0];
    #pragma unroll
    for (int w = 1; w < 8; w++) mAll = fmaxf(mAll, sred[w]);

    float s = 0.0f;
    #pragma unroll
    for (int t = 0; t < 8; t++) {
        v[t].x = __expf(v[t].x - mAll);
        v[t].y = __expf(v[t].y - mAll);
        s += v[t].x + v[t].y;
    }
    #pragma unroll
    for (int o = 16; o > 0; o >>= 1)
        s += __shfl_xor_sync(0xffffffffu, s, o);
    __syncthreads();
    if ((tid & 31) == 0) sred[tid >> 5] = s;
    __syncthreads();
    float sAll = 0.0f;
    #pragma unroll
    for (int w = 0; w < 8; w++) sAll += sred[w];

    const float rr = 1.0f / sAll;
    #pragma unroll
    for (int t = 0; t < 8; t++) {
        __half2 h = __floats2half2_rn(v[t].x * rr, v[t].y * rr);
        *(__half2*)&P[t * 512 + tid * 2] = h;
    }
}

// ===========================================================================
// Kernel 4: out = prob @ feat^T via fp16 mma + cp.async 3-stage (unchanged).
// CTA: M=128(i) x N=256(c), K=4096 (Kt=64 halves, 64 iters).
// ===========================================================================
#define OH_LD 72
#define O_ABYTES (128 * OH_LD * 2)
#define O_STAGE  (O_ABYTES + 256 * OH_LD * 2)  // 55296
#define O_SMEM   (3 * O_STAGE)                 // 165888
#define O_NIT    64

__global__ __launch_bounds__(256, 1)
void out_mma_kernel(const float* __restrict__ mask, float* __restrict__ out) {
    extern __shared__ char smc[];
    const uint32_t sb = smem_u32(smc);
    const int tid  = threadIdx.x;
    const int wid  = tid >> 5, lane = tid & 31;
    const int n  = blockIdx.y;
    const int i0 = blockIdx.x * 128;
    const __half* Pg = g_prob   + (size_t)n * HW * HW;   // [i][j]
    const __half* F  = g_feat_h + (size_t)n * COUT * HW; // [c][j]

    auto load_stage = [&](int s, int kt) {
        uint32_t base = sb + (uint32_t)s * O_STAGE;
        #pragma unroll
        for (int idx = tid; idx < 3072; idx += 256) {
            if (idx < 1024) {
                int row = idx >> 3, ch = idx & 7;
                CP16(base + row * 144 + ch * 16,
                     Pg + (size_t)(i0 + row) * HW + kt + ch * 8);
            } else {
                int q = idx - 1024;
                int row = q >> 3, ch = q & 7;
                CP16(base + O_ABYTES + row * 144 + ch * 16,
                     F + (size_t)row * HW + kt + ch * 8);
            }
        }
        CP_COMMIT();
    };

    load_stage(0, 0);
    load_stage(1, 64);

    const int wm = wid & 1, wn = wid >> 1;
    const int r = lane >> 2, kq = lane & 3;
    float cc[4][8][4] = {};

    for (int it = 0; it < O_NIT; ++it) {
        CP_WAIT1();
        __syncthreads();
        const __half* As = (const __half*)(smc + (it % 3) * O_STAGE);
        const __half* Bs = (const __half*)(smc + (it % 3) * O_STAGE + O_ABYTES);
        #pragma unroll
        for (int ks = 0; ks < 4; ks++) {
            const int k0 = ks * 16;
            uint32_t af[4][4];
            #pragma unroll
            for (int mt = 0; mt < 4; mt++) {
                int mb = wm * 64 + mt * 16;
                af[mt][0] = *(const uint32_t*)&As[(mb + r) * OH_LD + k0 + 2 * kq];
                af[mt][1] = *(const uint32_t*)&As[(mb + r + 8) * OH_LD + k0 + 2 * kq];
                af[mt][2] = *(const uint32_t*)&As[(mb + r) * OH_LD + k0 + 2 * kq + 8];
                af[mt][3] = *(const uint32_t*)&As[(mb + r + 8) * OH_LD + k0 + 2 * kq + 8];
            }
            #pragma unroll
            for (int nt = 0; nt < 8; nt++) {
                int nb = wn * 64 + nt * 8;
                uint32_t b0 = *(const uint32_t*)&Bs[(nb + r) * OH_LD + k0 + 2 * kq];
                uint32_t b1 = *(const uint32_t*)&Bs[(nb + r) * OH_LD + k0 + 2 * kq + 8];
                #pragma unroll
                for (int mt = 0; mt < 4; mt++)
                    mma_f16(cc[mt][nt], af[mt][0], af[mt][1], af[mt][2], af[mt][3], b0, b1);
            }
        }
        __syncthreads();
        if (it + 2 < O_NIT) load_stage((it + 2) % 3, (it + 2) * 64);
        else CP_COMMIT();
    }
    CP_WAIT0();
    __syncthreads();

    // Stage C: S[c_local][i_local], stride 132; masked f32 store.
    float* S = (float*)smc;
    #pragma unroll
    for (int mt = 0; mt < 4; mt++) {
        int ib = wm * 64 + mt * 16 + r;
        #pragma unroll
        for (int nt = 0; nt < 8; nt++) {
            int cb = wn * 64 + nt * 8 + kq * 2;
            S[cb * 132 + ib]           = cc[mt][nt][0];
            S[(cb + 1) * 132 + ib]     = cc[mt][nt][1];
            S[cb * 132 + ib + 8]       = cc[mt][nt][2];
            S[(cb + 1) * 132 + ib + 8] = cc[mt][nt][3];
        }
    }
    __syncthreads();

    #pragma unroll 4
    for (int idx = tid; idx < 8192; idx += 256) {
        int row = idx >> 5, ch = idx & 31;
        int ii = i0 + ch * 4;
        float4 v = *(const float4*)&S[row * 132 + ch * 4];
        float4 mm = *(const float4*)&mask[(size_t)n * HW + ii];
        v.x *= mm.x; v.y *= mm.y; v.z *= mm.z; v.w *= mm.w;
        *(float4*)&out[((size_t)n * COUT + row) * HW + ii] = v;
    }
}

// ===========================================================================
extern "C" void kernel_launch(void* const* d_in, const int* in_sizes, int n_in,
                              void* d_out, int out_size) {
    const float* x           = (const float*)d_in[0];
    const float* mask        = (const float*)d_in[1];
    const float* reduc_w     = (const float*)d_in[2];
    const float* reduc_gamma = (const float*)d_in[3];
    const float* reduc_beta  = (const float*)d_in[4];
    const float* reduc_mean  = (const float*)d_in[5];
    const float* reduc_var   = (const float*)d_in[6];
    const float* att_w       = (const float*)d_in[7];
    const float* att_gamma   = (const float*)d_in[8];
    const float* att_beta    = (const float*)d_in[9];
    const float* att_mean    = (const float*)d_in[10];
    const float* att_var     = (const float*)d_in[11];
    float* out = (float*)d_out;

    cudaFuncSetAttribute(conv_mma_kernel,   cudaFuncAttributeMaxDynamicSharedMemorySize, V_SMEM);
    cudaFuncSetAttribute(energy_mma_kernel, cudaFuncAttributeMaxDynamicSharedMemorySize, E_SMEM);
    cudaFuncSetAttribute(out_mma_kernel,    cudaFuncAttributeMaxDynamicSharedMemorySize, O_SMEM);

    prep_x_kernel<<<dim3(HW / 64, CIN / 64, NB), 256>>>(x);
    prep_w_kernel<<<384, 256>>>(reduc_w, att_w);

    conv_mma_kernel<<<dim3(HW / 256, 3, NB), 256, V_SMEM>>>(
        reduc_gamma, reduc_beta, reduc_mean, reduc_var,
        att_gamma, att_beta, att_mean, att_var);

    energy_mma_kernel<<<dim3(HW / 256, HW / 128, NB), 256, E_SMEM>>>(mask);

    softmax_kernel<<<NB * HW, 256>>>();

    out_mma_kernel<<<dim3(HW / 128, NB), 256, O_SMEM>>>(mask, out);
}